// round 10
// baseline (speedup 1.0000x reference)
#include <cuda_runtime.h>
#include <cuda_bf16.h>
#include <cstdint>

// ESN: h_t = tanh(x_t @ W_in^T + h_{t-1} @ W_res^T); out = h_{T-1} [B,H] fp32.
// B=64, T=512, I=128, H=2048.
//
// Round 10: round-9 numerics/sync, MMA re-tiled to cut LDS traffic:
// 16 warps = 4 j-tiles(32j) x 2 b-halves(32b) x 2 k-halves. Per kc only 8
// warps load frags (32KB/kc vs 48). k-half 1 dumps fp32 accs into a swizzled
// smem buffer (reuses dead v region); k-half 0 adds and stores partials.

#define BB   64
#define TT   512
#define II   128
#define HH   2048
#define NJG  16
#define NKS  9
#define KC1  256
#define NTHR 512
#define NCTA (NJG * NKS)          // 144
#define ASTRIDE 528               // bytes per j-row (512 data + 16 pad)
#define TSZA (128 * ASTRIDE)      // 67584 per W term
#define BSTRIDE 528
#define TSZB (BB * BSTRIDE)       // 33792 per v term
#define BOFF (2 * TSZA)
#define SLOT (2 * TSZA)
#define DYN_SMEM (2 * TSZA + 2 * TSZB)   // 202752

// ---------------- device globals ----------------
__device__ __align__(16) unsigned char  g_wt[NCTA * SLOT];
__device__ __align__(16) __nv_bfloat16  g_xh[BB * TT * II];
__device__ __align__(16) __nv_bfloat16  g_xl[BB * TT * II];
__device__ __align__(16) __nv_bfloat16  g_hh[2][BB * HH];
__device__ __align__(16) __nv_bfloat16  g_hl[2][BB * HH];
__device__ float    g_part[2][NKS * NJG * 128 * BB];   // ping-pong by t&1
__device__ unsigned g_pcnt[NJG];   // partials stored, per jg (9/step)
__device__ unsigned g_hcnt[8];     // h slice written, per slice (16/step)

// ---------------- asm helpers ----------------
__device__ __forceinline__ void mma_bf16(float* d, const uint32_t* a,
                                         uint32_t b0, uint32_t b1) {
    asm volatile(
        "mma.sync.aligned.m16n8k16.row.col.f32.bf16.bf16.f32 "
        "{%0,%1,%2,%3}, {%4,%5,%6,%7}, {%8,%9}, {%0,%1,%2,%3};"
        : "+f"(d[0]), "+f"(d[1]), "+f"(d[2]), "+f"(d[3])
        : "r"(a[0]), "r"(a[1]), "r"(a[2]), "r"(a[3]), "r"(b0), "r"(b1));
}
__device__ __forceinline__ void ldmx4(uint32_t* r, uint32_t addr) {
    asm volatile("ldmatrix.sync.aligned.m8n8.x4.shared.b16 {%0,%1,%2,%3}, [%4];"
        : "=r"(r[0]), "=r"(r[1]), "=r"(r[2]), "=r"(r[3]) : "r"(addr));
}
__device__ __forceinline__ uint32_t smem_u32(const void* p) {
    uint32_t a;
    asm("{ .reg .u64 t; cvta.to.shared.u64 t, %1; cvt.u32.u64 %0, t; }"
        : "=r"(a) : "l"(p));
    return a;
}
__device__ __forceinline__ void flag_add(unsigned* p) {
    asm volatile("red.release.gpu.global.add.u32 [%0], 1;" :: "l"(p) : "memory");
}
__device__ __forceinline__ void spin_ge(unsigned* c, unsigned tgt) {
    unsigned v;
    do {
        asm volatile("ld.acquire.gpu.global.u32 %0, [%1];"
                     : "=r"(v) : "l"(c) : "memory");
    } while (v < tgt);
}

// ---------------- prep ----------------
__global__ void esn_prep_w(const float* __restrict__ Win, const float* __restrict__ Wres) {
    const int total = HH * (II + HH);
    for (int idx = blockIdx.x * blockDim.x + threadIdx.x; idx < total;
         idx += gridDim.x * blockDim.x) {
        int j = idx / (II + HH);
        int k = idx % (II + HH);
        int jg = j >> 7, jl = j & 127;
        int ks, kl;
        float w;
        if (k < II) { ks = 0; kl = k; w = Win[j * II + k]; }
        else { int kk = k - II; ks = 1 + (kk >> 8); kl = kk & 255; w = Wres[j * HH + kk]; }
        __nv_bfloat16 hi = __float2bfloat16(w);
        float r = w - __bfloat162float(hi);
        __nv_bfloat16 lo = __float2bfloat16(r);
        unsigned base = (unsigned)(jg * NKS + ks) * SLOT + (unsigned)jl * ASTRIDE + (unsigned)kl * 2;
        *(__nv_bfloat16*)(g_wt + base)        = hi;
        *(__nv_bfloat16*)(g_wt + base + TSZA) = lo;
    }
}

__global__ void esn_prep_x(const float* __restrict__ x) {
    const int total = BB * TT * II;
    for (int idx = blockIdx.x * blockDim.x + threadIdx.x; idx < total;
         idx += gridDim.x * blockDim.x) {
        float v = x[idx];
        __nv_bfloat16 hi = __float2bfloat16(v);
        float r = v - __bfloat162float(hi);
        g_xh[idx] = hi;
        g_xl[idx] = __float2bfloat16(r);
    }
}

__global__ void esn_cnt0() {
    int i = threadIdx.x;
    if (i < NJG) g_pcnt[i] = 0u;
    if (i < 8)  g_hcnt[i] = 0u;
}

// ---------------- persistent kernel ----------------
__global__ __launch_bounds__(NTHR, 1) void esn_run(float* __restrict__ out) {
    extern __shared__ __align__(16) unsigned char sm[];
    __shared__ float sT[16 * 65];

    const int tid  = threadIdx.x;
    const int wid  = tid >> 5;
    const int l    = tid & 31;
    const int wj   = wid >> 2;            // 0..3: 32-row j tile
    const int wb   = (wid >> 1) & 1;      // 0..1: 32-col b half
    const int wk   = wid & 1;             // 0..1: k half
    const int bid  = blockIdx.x;
    const int jg   = bid / NKS;
    const int ks   = bid % NKS;
    const int KC   = ks ? KC1 : II;
    const int kch  = KC >> 4;
    const int cpb  = KC >> 3;             // 16B chunks per b-row
    const int chunks = BB * cpb;

    const uint32_t smA = smem_u32(sm);
    const uint32_t smB = smA + BOFF;
    float* const cb = (float*)(sm + BOFF);   // combine buffer (reuses v region)

    // ldmatrix lane bases
    const uint32_t aA = smA + (uint32_t)(wj * 32 + ((l >> 3) & 1) * 8 + (l & 7)) * ASTRIDE
                            + (uint32_t)(l >> 4) * 16;
    const uint32_t aB = smB + (uint32_t)(wb * 32 + ((l >> 4) & 1) * 8 + (l & 7)) * BSTRIDE
                            + (uint32_t)((l >> 3) & 1) * 16;

    // ---- load W slot (hi + lo) into smem once ----
    {
        const uint4* src = (const uint4*)(g_wt + (unsigned)(jg * NKS + ks) * SLOT);
        uint4* dst = (uint4*)sm;
        for (int i = tid; i < SLOT / 16; i += NTHR) dst[i] = src[i];
    }

    // reduce-role constants (bid 0..127): 16j x 64b tile
    const int r_jg = bid >> 3;
    const int r_8  = bid & 7;
    const int r_s  = r_jg >> 1;
    const int jt   = tid >> 5;             // 0..15
    const int b2   = (tid & 31) * 2;       // 0..62

    // acc->(j,b) lane mapping
    const int jrr = l >> 2;                // 0..7
    const int bcc = (l & 3) * 2;           // 0..6

    // ---- stage v_0: ks==0 from x[0], else zeros (h_{-1} = 0) ----
    if (ks == 0) {
        for (int i = tid; i < chunks; i += NTHR) {
            int b = i / cpb, c = i - b * cpb;
            int e = (b * TT + 0) * II + c * 8;
            uint32_t d = (uint32_t)(BOFF + b * BSTRIDE + c * 16);
            *(uint4*)(sm + d)        = *(const uint4*)(g_xh + e);
            *(uint4*)(sm + d + TSZB) = *(const uint4*)(g_xl + e);
        }
    } else {
        const uint4 z = make_uint4(0u, 0u, 0u, 0u);
        for (int i = tid; i < chunks; i += NTHR) {
            int b = i / cpb, c = i - b * cpb;
            uint32_t d = (uint32_t)(BOFF + b * BSTRIDE + c * 16);
            *(uint4*)(sm + d)        = z;
            *(uint4*)(sm + d + TSZB) = z;
        }
    }
    __syncthreads();

    for (int t = 0; t < TT; t++) {
        // ---- MMA: warp = 32j x 32b, k-half = wk; 3 terms ----
        float acc[2][4][4];
#pragma unroll
        for (int mi = 0; mi < 2; mi++)
#pragma unroll
            for (int nf = 0; nf < 4; nf++)
#pragma unroll
                for (int i = 0; i < 4; i++) acc[mi][nf][i] = 0.0f;

#pragma unroll 2
        for (int kc = wk; kc < kch; kc += 2) {
            const uint32_t ka = (uint32_t)kc * 32;
            uint32_t Ah[2][4], Al[2][4], Bh[2][4], Bl[2][4];
            ldmx4(Ah[0], aA + ka);
            ldmx4(Ah[1], aA + 16 * ASTRIDE + ka);
            ldmx4(Al[0], aA + TSZA + ka);
            ldmx4(Al[1], aA + TSZA + 16 * ASTRIDE + ka);
            ldmx4(Bh[0], aB + ka);
            ldmx4(Bh[1], aB + 16 * BSTRIDE + ka);
            ldmx4(Bl[0], aB + TSZB + ka);
            ldmx4(Bl[1], aB + TSZB + 16 * BSTRIDE + ka);
#pragma unroll
            for (int mi = 0; mi < 2; mi++)
#pragma unroll
                for (int nf = 0; nf < 4; nf++) {
                    const int ni = nf >> 1, h8 = (nf & 1) * 2;
                    mma_bf16(acc[mi][nf], Ah[mi], Bh[ni][h8], Bh[ni][h8 + 1]);
                    mma_bf16(acc[mi][nf], Ah[mi], Bl[ni][h8], Bl[ni][h8 + 1]);
                    mma_bf16(acc[mi][nf], Al[mi], Bh[ni][h8], Bh[ni][h8 + 1]);
                }
        }

        __syncthreads();                    // all frag reads done (v region now dead)

        // ---- k-half 1: dump accs to swizzled smem combine buffer ----
        // layout: row (0..127) x 32 float2 slots; slot' = slot ^ ((row&7)<<2)
        if (wk == 1) {
#pragma unroll
            for (int mi = 0; mi < 2; mi++)
#pragma unroll
                for (int nf = 0; nf < 4; nf++) {
                    const int slot = wb * 16 + nf * 4 + (l & 3);
                    const int r0 = wj * 32 + mi * 16 + jrr;
                    const int r1 = r0 + 8;
                    *(float2*)&cb[r0 * 64 + ((slot ^ ((r0 & 7) << 2)) << 1)] =
                        make_float2(acc[mi][nf][0], acc[mi][nf][1]);
                    *(float2*)&cb[r1 * 64 + ((slot ^ ((r1 & 7) << 2)) << 1)] =
                        make_float2(acc[mi][nf][2], acc[mi][nf][3]);
                }
        }
        __syncthreads();

        // ---- k-half 0: add combine buffer, store partials (.cg) ----
        if (wk == 0) {
            float* P = g_part[t & 1] + (unsigned)(ks * NJG + jg) * (128 * BB);
#pragma unroll
            for (int mi = 0; mi < 2; mi++)
#pragma unroll
                for (int nf = 0; nf < 4; nf++) {
                    const int slot = wb * 16 + nf * 4 + (l & 3);
                    const int r0 = wj * 32 + mi * 16 + jrr;
                    const int r1 = r0 + 8;
                    const float2 c0 = *(const float2*)&cb[r0 * 64 + ((slot ^ ((r0 & 7) << 2)) << 1)];
                    const float2 c1 = *(const float2*)&cb[r1 * 64 + ((slot ^ ((r1 & 7) << 2)) << 1)];
                    const int b = wb * 32 + nf * 8 + bcc;
                    __stcg((float2*)&P[r0 * BB + b],
                           make_float2(acc[mi][nf][0] + c0.x, acc[mi][nf][1] + c0.y));
                    __stcg((float2*)&P[r1 * BB + b],
                           make_float2(acc[mi][nf][2] + c1.x, acc[mi][nf][3] + c1.y));
                }
        }
        __syncthreads();                    // P stores done; cb reads done
        if (tid == 0) flag_add(&g_pcnt[jg]);

        // ---- reduce role (bid 0..127): 16j x 64b tile ----
        if (bid < 128) {
            if (tid == 0) spin_ge(&g_pcnt[r_jg], 9u * (t + 1));
            __syncthreads();

            const unsigned o = (unsigned)((r_8 * 16 + jt) * 64 + b2);
            float s0 = 0.f, s1 = 0.f;
            const float* Pb = g_part[t & 1];
#pragma unroll
            for (int kr = 0; kr < NKS; kr++) {
                const float2 v = __ldcg((const float2*)
                    (Pb + (unsigned)(kr * NJG + r_jg) * (128 * BB) + o));
                s0 += v.x; s1 += v.y;
            }
            s0 = tanhf(s0); s1 = tanhf(s1);
            sT[jt * 65 + b2]     = s0;
            sT[jt * 65 + b2 + 1] = s1;
            __syncthreads();                // transpose handoff

            __nv_bfloat16* hh = g_hh[t & 1];
            __nv_bfloat16* hl = g_hl[t & 1];
            const bool last_t = (t == TT - 1);
            {
                const int p  = tid & 7;     // j pair
                const int bb = tid >> 3;    // batch
                const float f0 = sT[(2 * p) * 65 + bb];
                const float f1 = sT[(2 * p + 1) * 65 + bb];
                const int jglob = r_jg * 128 + r_8 * 16 + 2 * p;
                __nv_bfloat162 h2 = __floats2bfloat162_rn(f0, f1);
                float r0 = f0 - __bfloat162float(__low2bfloat16(h2));
                float r1 = f1 - __bfloat162float(__high2bfloat16(h2));
                __nv_bfloat162 l2 = __floats2bfloat162_rn(r0, r1);
                __stcg((unsigned*)(hh + bb * HH + jglob), *(unsigned*)&h2);
                __stcg((unsigned*)(hl + bb * HH + jglob), *(unsigned*)&l2);
                if (last_t) *(float2*)&out[bb * HH + jglob] = make_float2(f0, f1);
            }
            __syncthreads();                // all h stores done before flag
            if (tid == 0) flag_add(&g_hcnt[r_s]);
        }

        // ---- stage v_{t+1} ----
        if (t + 1 < TT) {
            if (tid == 0) {
                // P WAR: reducers of my jg done with step t-1 (buffer (t+1)&1)
                if (t >= 1) spin_ge(&g_hcnt[jg >> 1], 16u * t);
                // RAW: h_t slice ready
                if (ks) spin_ge(&g_hcnt[ks - 1], 16u * (t + 1));
            }
            __syncthreads();

            if (ks == 0) {
                for (int i = tid; i < chunks; i += NTHR) {
                    int b = i / cpb, c = i - b * cpb;
                    int e = (b * TT + (t + 1)) * II + c * 8;
                    uint32_t d = (uint32_t)(BOFF + b * BSTRIDE + c * 16);
                    *(uint4*)(sm + d)        = *(const uint4*)(g_xh + e);
                    *(uint4*)(sm + d + TSZB) = *(const uint4*)(g_xl + e);
                }
            } else {
                const __nv_bfloat16* hh = g_hh[t & 1];
                const __nv_bfloat16* hl = g_hl[t & 1];
                for (int i = tid; i < chunks; i += NTHR) {
                    int b = i / cpb, c = i - b * cpb;
                    int e = b * HH + (ks - 1) * KC1 + c * 8;
                    uint32_t d = (uint32_t)(BOFF + b * BSTRIDE + c * 16);
                    *(uint4*)(sm + d)        = __ldcg((const uint4*)(hh + e));
                    *(uint4*)(sm + d + TSZB) = __ldcg((const uint4*)(hl + e));
                }
            }
            __syncthreads();                // v staged before next MMA
        }
    }
}

// ---------------- launcher ----------------
extern "C" void kernel_launch(void* const* d_in, const int* in_sizes, int n_in,
                              void* d_out, int out_size)
{
    const float* x    = (const float*)d_in[0];
    const float* Win  = (const float*)d_in[1];
    const float* Wres = (const float*)d_in[2];
    float* out = (float*)d_out;

    cudaFuncSetAttribute(esn_run, cudaFuncAttributeMaxDynamicSharedMemorySize, DYN_SMEM);

    esn_prep_w<<<2048, 256>>>(Win, Wres);
    esn_prep_x<<<2048, 256>>>(x);
    esn_cnt0<<<1, 32>>>();
    esn_run<<<NCTA, NTHR, DYN_SMEM>>>(out);
}